// round 1
// baseline (speedup 1.0000x reference)
#include <cuda_runtime.h>

// DropStripes: x (64, 2048, 512) fp32, zero 2 random stripes along dim 2 per batch.
// out[b, t, c] = x[b, t, c] * keep[b, c]
//   d_s  = floor(u_dist[b,s] * 64)
//   bgn_s = floor(u_bgn[b,s] * (512 - d_s))
//   keep[b,c] = !(any_s: bgn_s <= c < bgn_s + d_s)
//
// Pure HBM-bound streaming op: 256 MB in + 256 MB out.
// float4 vectorized, exact grid, no divides (power-of-two shifts).

#define TOTAL_ELEMS (64 * 2048 * 512)
#define N4          (TOTAL_ELEMS / 4)     // 16,777,216 float4s
#define C4_MASK     127                   // 512/4 - 1 channel-groups per row
#define B_SHIFT     18                    // float4s per batch = 2048*128 = 2^18

__global__ void __launch_bounds__(256) drop_stripes_kernel(
    const float4* __restrict__ x,
    const float*  __restrict__ u_dist,
    const float*  __restrict__ u_bgn,
    float4*       __restrict__ out)
{
    int i = blockIdx.x * blockDim.x + threadIdx.x;   // float4 index, grid is exact
    int b = i >> B_SHIFT;                            // batch
    int c = (i & C4_MASK) << 2;                      // base channel of this float4

    // Stripe parameters for this batch (L1-resident after first touch).
    // Match jnp.floor(fp32 product) exactly.
    float ud0 = __ldg(&u_dist[2 * b + 0]);
    float ud1 = __ldg(&u_dist[2 * b + 1]);
    float ub0 = __ldg(&u_bgn [2 * b + 0]);
    float ub1 = __ldg(&u_bgn [2 * b + 1]);

    int d0 = (int)floorf(ud0 * 64.0f);
    int d1 = (int)floorf(ud1 * 64.0f);
    int s0 = (int)floorf(ub0 * (float)(512 - d0));
    int s1 = (int)floorf(ub1 * (float)(512 - d1));
    int e0 = s0 + d0;
    int e1 = s1 + d1;

    float4 v = x[i];

    // keep(c) = !((s0<=c<e0) || (s1<=c<e1))
    #pragma unroll
    {
        int c0 = c, c1 = c + 1, c2 = c + 2, c3 = c + 3;
        bool k0 = !((c0 >= s0 && c0 < e0) || (c0 >= s1 && c0 < e1));
        bool k1 = !((c1 >= s0 && c1 < e0) || (c1 >= s1 && c1 < e1));
        bool k2 = !((c2 >= s0 && c2 < e0) || (c2 >= s1 && c2 < e1));
        bool k3 = !((c3 >= s0 && c3 < e0) || (c3 >= s1 && c3 < e1));
        v.x = k0 ? v.x : 0.0f;
        v.y = k1 ? v.y : 0.0f;
        v.z = k2 ? v.z : 0.0f;
        v.w = k3 ? v.w : 0.0f;
    }

    out[i] = v;
}

extern "C" void kernel_launch(void* const* d_in, const int* in_sizes, int n_in,
                              void* d_out, int out_size)
{
    const float4* x      = (const float4*)d_in[0];
    const float*  u_dist = (const float*) d_in[1];
    const float*  u_bgn  = (const float*) d_in[2];
    float4*       out    = (float4*)      d_out;

    const int threads = 256;
    const int blocks  = N4 / threads;    // 65,536 — exact, no tail
    drop_stripes_kernel<<<blocks, threads>>>(x, u_dist, u_bgn, out);
}

// round 2
// speedup vs baseline: 1.0492x; 1.0492x over previous
#include <cuda_runtime.h>

// DropStripes: x (64, 2048, 512) fp32; zero 2 random channel-stripes per batch.
// out[b,t,c] = x[b,t,c] * keep[b,c]   (keep independent of t)
//
// Round-2: each thread handles 4 rows (t, t+1, t+2, t+3) at one (b, channel
// group of 4). One mask computation amortized over 4 float4s; loads batched
// front-first for MLP=4; streaming cache hints (no reuse in 512MB stream).
//
// Index math (all power-of-two):
//   row = 128 float4s (512 ch / 4). batch = 2048 rows.
//   thread slot i0 in [0, N4/4): c4 = i0 & 127; (t_hi,b) = i0 >> 7
//   base float4 idx = ((i0 >> 7) << 9) | (i0 & 127); rows at +0,+128,+256,+384

#define TOTAL_ELEMS (64 * 2048 * 512)
#define N4          (TOTAL_ELEMS / 4)     // 16,777,216 float4s
#define SLOTS       (N4 / 4)              // 4,194,304 thread slots

__global__ void __launch_bounds__(256) drop_stripes_kernel(
    const float4* __restrict__ x,
    const float*  __restrict__ u_dist,
    const float*  __restrict__ u_bgn,
    float4*       __restrict__ out)
{
    int i0 = blockIdx.x * blockDim.x + threadIdx.x;   // exact grid, no tail
    int c4   = i0 & 127;                   // channel-group within row
    int rest = i0 >> 7;                    // (b, t_hi)
    int b    = i0 >> 16;                   // batch (rest >> 9)
    long base = ((long)rest << 9) | c4;    // float4 index of row t_hi*4

    // Batch all 4 loads first: MLP=4, hides DRAM latency.
    float4 v0 = __ldcs(&x[base]);
    float4 v1 = __ldcs(&x[base + 128]);
    float4 v2 = __ldcs(&x[base + 256]);
    float4 v3 = __ldcs(&x[base + 384]);

    // Stripe mask for this batch — computed once, applies to all 4 rows.
    // Must match jnp.floor on fp32 products exactly.
    float ud0 = __ldg(&u_dist[2 * b + 0]);
    float ud1 = __ldg(&u_dist[2 * b + 1]);
    float ub0 = __ldg(&u_bgn [2 * b + 0]);
    float ub1 = __ldg(&u_bgn [2 * b + 1]);

    int d0 = (int)floorf(ud0 * 64.0f);
    int d1 = (int)floorf(ud1 * 64.0f);
    int s0 = (int)floorf(ub0 * (float)(512 - d0));
    int s1 = (int)floorf(ub1 * (float)(512 - d1));
    int e0 = s0 + d0;
    int e1 = s1 + d1;

    int c = c4 << 2;
    float k0 = ((c   >= s0 && c   < e0) || (c   >= s1 && c   < e1)) ? 0.0f : 1.0f;
    float k1 = ((c+1 >= s0 && c+1 < e0) || (c+1 >= s1 && c+1 < e1)) ? 0.0f : 1.0f;
    float k2 = ((c+2 >= s0 && c+2 < e0) || (c+2 >= s1 && c+2 < e1)) ? 0.0f : 1.0f;
    float k3 = ((c+3 >= s0 && c+3 < e0) || (c+3 >= s1 && c+3 < e1)) ? 0.0f : 1.0f;

    v0.x *= k0; v0.y *= k1; v0.z *= k2; v0.w *= k3;
    v1.x *= k0; v1.y *= k1; v1.z *= k2; v1.w *= k3;
    v2.x *= k0; v2.y *= k1; v2.z *= k2; v2.w *= k3;
    v3.x *= k0; v3.y *= k1; v3.z *= k2; v3.w *= k3;

    __stcs(&out[base],       v0);
    __stcs(&out[base + 128], v1);
    __stcs(&out[base + 256], v2);
    __stcs(&out[base + 384], v3);
}

extern "C" void kernel_launch(void* const* d_in, const int* in_sizes, int n_in,
                              void* d_out, int out_size)
{
    const float4* x      = (const float4*)d_in[0];
    const float*  u_dist = (const float*) d_in[1];
    const float*  u_bgn  = (const float*) d_in[2];
    float4*       out    = (float4*)      d_out;

    const int threads = 256;
    const int blocks  = SLOTS / threads;   // 16,384 — exact, no tail
    drop_stripes_kernel<<<blocks, threads>>>(x, u_dist, u_bgn, out);
}